// round 6
// baseline (speedup 1.0000x reference)
#include <cuda_runtime.h>
#include <math.h>

// ---------------------------------------------------------------------------
// Shapes: N=16, F=5, V=4 -> 320 images of 3x224x224
// conv1: 3->3, 3x3, s2: 224->111 ; maxpool3/3 -> 37 ; relu
// conv2: 3->1, 3x3, s2: 37->18   ; maxpool3/3 -> 6  ; relu
// flatten 36 -> linear -> feat[320,6]; graph ops + MLP -> [16,6]
//
// ONE kernel, 1712 blocks x 256 threads (R4's conv1 grid = best measured DRAM
// utilization). Phase A: every thread computes one conv1+pool output -> g_h1.
// Ticketing: the last 320 blocks to finish phase A each run conv2+linear for
// one image; the last 16 of those run the graph+readout. Spinners are always
// the last finishers -> negligible wait; 320 spinners < 444 resident slots.
// ---------------------------------------------------------------------------

#define NIMG 320
#define H1_STRIDE (3 * 1369)
#define TOTAL1 (NIMG * 1369)          // 438080 conv1 outputs
#define NBLK 1712                     // ceil(TOTAL1/256)

__device__ float g_h1[NIMG * H1_STRIDE];
__device__ float g_feat[NIMG * 6];
__device__ int g_c1 = 0, g_t1 = 0, g_cf = 0, g_t2 = 0, g_r = 0;

__global__ __launch_bounds__(256, 3)
void fused_kernel(const float* __restrict__ nodes,
                  const float* __restrict__ pos,     // [16,5,4,6]
                  const float* __restrict__ attmap,  // [16,5,4,4]
                  const float* __restrict__ c1w, const float* __restrict__ c1b,
                  const float* __restrict__ c2w, const float* __restrict__ c2b,
                  const float* __restrict__ lw,  const float* __restrict__ lb,
                  const float* __restrict__ wfc_w, const float* __restrict__ wfc_b,
                  const float* __restrict__ fm_w,  const float* __restrict__ fm_b,
                  const float* __restrict__ lm_w,  const float* __restrict__ lm_b,
                  const float* __restrict__ fc1_w, const float* __restrict__ fc1_b,
                  const float* __restrict__ fc2_w, const float* __restrict__ fc2_b,
                  const float* __restrict__ fc3_w, const float* __restrict__ fc3_b,
                  float* __restrict__ out)           // [16,6]
{
    __shared__ float sw[81];
    __shared__ float sb[3];
    __shared__ int   s_tick;
    __shared__ float sw2[27];
    __shared__ float s_conv[36][9];
    __shared__ float s_hs[36];
    __shared__ float r_feat[20][6];
    __shared__ float r_ps[20][6];
    __shared__ float r_asrc[20];
    __shared__ float r_btgt[20];
    __shared__ float r_pm[20][6];
    __shared__ float r_inp[240];
    __shared__ float r_part[240];
    __shared__ float r_r1[120];
    __shared__ float r_r2[60];

    const int t = threadIdx.x;
    if (t < 81) sw[t] = c1w[t];
    if (t < 3)  sb[t] = c1b[t];
    __syncthreads();

    // ---------------- Phase A: conv1(s2) + maxpool3 + relu (R4 shape) -------
    int idx = blockIdx.x * 256 + t;
    if (idx < TOTAL1) {
        int px  = idx % 37;
        int rem = idx / 37;
        int py  = rem % 37;
        int img = rem / 37;
        const float* base = nodes + (size_t)img * 150528
                                  + (size_t)(6 * py) * 224 + 6 * px;
        float acc[9][3];
#pragma unroll
        for (int p = 0; p < 9; p++) {
            acc[p][0] = sb[0]; acc[p][1] = sb[1]; acc[p][2] = sb[2];
        }
#pragma unroll
        for (int ic = 0; ic < 3; ic++) {
            const float* chan = base + ic * 50176;
            float2 p2[7][4];
#pragma unroll
            for (int r = 0; r < 7; r++) {
                const float* rp = chan + r * 224;
                p2[r][0] = *(const float2*)(rp);
                p2[r][1] = *(const float2*)(rp + 2);
                p2[r][2] = *(const float2*)(rp + 4);
                p2[r][3] = *(const float2*)(rp + 6);
            }
#pragma unroll
            for (int ky = 0; ky < 3; ky++)
#pragma unroll
                for (int kx = 0; kx < 3; kx++) {
                    float w0 = sw[ic * 9 + ky * 3 + kx];
                    float w1 = sw[27 + ic * 9 + ky * 3 + kx];
                    float w2 = sw[54 + ic * 9 + ky * 3 + kx];
#pragma unroll
                    for (int cy = 0; cy < 3; cy++)
#pragma unroll
                        for (int cx = 0; cx < 3; cx++) {
                            int col = 2 * cx + kx;
                            float v = (col & 1) ? p2[2 * cy + ky][col >> 1].y
                                                : p2[2 * cy + ky][col >> 1].x;
                            acc[cy * 3 + cx][0] += v * w0;
                            acc[cy * 3 + cx][1] += v * w1;
                            acc[cy * 3 + cx][2] += v * w2;
                        }
                }
        }
#pragma unroll
        for (int oc = 0; oc < 3; oc++) {
            float m = acc[0][oc];
#pragma unroll
            for (int p = 1; p < 9; p++) m = fmaxf(m, acc[p][oc]);
            int img2 = idx / 1369, o = idx % 1369;
            g_h1[(size_t)img2 * H1_STRIDE + oc * 1369 + o] = fmaxf(m, 0.0f);
        }
    }
    __threadfence();
    __syncthreads();
    if (t == 0) {
        atomicAdd(&g_c1, 1);
        s_tick = atomicAdd(&g_t1, 1);
    }
    __syncthreads();
    int tick = s_tick;
    if (tick < NBLK - NIMG) return;     // not one of the last 320 finishers

    // ---------------- Phase B: conv2 + maxpool3 + relu + linear -------------
    const int img = tick - (NBLK - NIMG);
    if (t < 27) sw2[t] = c2w[t];
    if (t == 0) {
        while (atomicAdd(&g_c1, 0) < NBLK) __nanosleep(64);
    }
    __syncthreads();
    __threadfence();

    for (int posn = t; posn < 324; posn += 256) {
        int pool = posn / 9, cp = posn - pool * 9;
        int py = pool / 6, px = pool - py * 6;
        int cy = 3 * py + cp / 3;
        int cx = 3 * px + cp % 3;
        const float* src = g_h1 + (size_t)img * H1_STRIDE + (2 * cy) * 37 + 2 * cx;
        float s = __ldg(c2b);
#pragma unroll
        for (int ic = 0; ic < 3; ic++)
#pragma unroll
            for (int ky = 0; ky < 3; ky++)
#pragma unroll
                for (int kx = 0; kx < 3; kx++)
                    s += src[ic * 1369 + ky * 37 + kx] * sw2[ic * 9 + ky * 3 + kx];
        s_conv[pool][cp] = s;
    }
    __syncthreads();
    if (t < 36) {
        float m = s_conv[t][0];
#pragma unroll
        for (int p = 1; p < 9; p++) m = fmaxf(m, s_conv[t][p]);
        s_hs[t] = fmaxf(m, 0.0f);
    }
    __syncthreads();
    if (t < 6) {
        float s = __ldg(lb + t);
#pragma unroll
        for (int i = 0; i < 36; i++) s += s_hs[i] * __ldg(lw + i * 6 + t);
        g_feat[img * 6 + t] = s;
    }
    __threadfence();
    __syncthreads();
    if (t == 0) {
        atomicAdd(&g_cf, 1);
        s_tick = atomicAdd(&g_t2, 1);
    }
    __syncthreads();
    int tick2 = s_tick;
    if (tick2 < NIMG - 16) return;      // not one of the last 16

    // ---------------- Phase C: graph ops + readout MLP ----------------------
    const int n = tick2 - (NIMG - 16);
    if (t == 0) {
        while (atomicAdd(&g_cf, 0) < NIMG) __nanosleep(64);
    }
    __syncthreads();
    __threadfence();

    if (t < 120) {
        int fv = t / 6, d = t % 6;
        r_feat[fv][d] = g_feat[(n * 20 + fv) * 6 + d];
        r_ps[fv][d]   = pos[(n * 20 + fv) * 6 + d];
    }
    __syncthreads();

    if (t < 20) {
        float a = 0.0f, bb = 0.0f;
#pragma unroll
        for (int k = 0; k < 6; k++) {
            a  += r_feat[t][k] * wfc_w[k]      + r_ps[t][k] * wfc_w[6 + k];
            bb += r_feat[t][k] * wfc_w[12 + k] + r_ps[t][k] * wfc_w[18 + k];
        }
        r_asrc[t] = a;
        r_btgt[t] = bb;
    }
    if (t < 120) {
        int fv = t / 6, d = t % 6;
        float s = fm_b[d];
#pragma unroll
        for (int k = 0; k < 6; k++) s += r_ps[fv][k] * fm_w[k * 6 + d];
        r_pm[fv][d] = s;
    }
    __syncthreads();

    if (t < 120) {
        int fv = t / 6, d = t % 6;
        int f = fv / 4, tv = fv % 4;
        float bias = wfc_b[0];
        float agg = 0.0f;
#pragma unroll
        for (int s = 0; s < 4; s++) {
            float z  = r_asrc[f * 4 + s] + r_btgt[f * 4 + tv] + bias;
            float lk = 1.0f / (1.0f + expf(-z));
            float m  = lk + attmap[((n * 5 + f) * 4 + s) * 4 + tv];
            agg += m * r_pm[f * 4 + s][d];
        }
        if (f > 0) {
            float lm = lm_b[d];
#pragma unroll
            for (int k = 0; k < 6; k++) lm += r_ps[(f - 1) * 4 + tv][k] * lm_w[k * 6 + d];
            agg += lm;
        }
        r_inp[fv * 12 + d]     = r_feat[fv][d];
        r_inp[fv * 12 + 6 + d] = agg;
    }
    __syncthreads();

    if (t < 240) {                       // fc1 split over 2 halves
        int half = t / 120, j = t - half * 120;
        int i0 = half * 120;
        float s = 0.0f;
#pragma unroll 12
        for (int i = 0; i < 120; i++)
            s += r_inp[i0 + i] * __ldg(fc1_w + (i0 + i) * 120 + j);
        r_part[t] = s;
    }
    __syncthreads();
    if (t < 120) r_r1[t] = fmaxf(r_part[t] + r_part[120 + t] + __ldg(fc1_b + t), 0.0f);
    __syncthreads();

    if (t < 120) {                       // fc2 split over 2 halves
        int half = t / 60, j = t - half * 60;
        int i0 = half * 60;
        float s = 0.0f;
#pragma unroll 12
        for (int i = 0; i < 60; i++)
            s += r_r1[i0 + i] * __ldg(fc2_w + (i0 + i) * 60 + j);
        r_part[t] = s;
    }
    __syncthreads();
    if (t < 60) r_r2[t] = fmaxf(r_part[t] + r_part[60 + t] + __ldg(fc2_b + t), 0.0f);
    __syncthreads();

    if (t < 6) {
        float s = __ldg(fc3_b + t);
#pragma unroll
        for (int i = 0; i < 60; i++) s += r_r2[i] * __ldg(fc3_w + i * 6 + t);
        out[n * 6 + t] = s;
    }
    __syncthreads();

    // deterministic counter reset for graph replay (16th readout block)
    if (t == 0) {
        int r = atomicAdd(&g_r, 1);
        if (r == 15) {
            g_c1 = 0; g_t1 = 0; g_cf = 0; g_t2 = 0;
            __threadfence();
            g_r = 0;
        }
    }
}

// ---------------------------------------------------------------------------
extern "C" void kernel_launch(void* const* d_in, const int* in_sizes, int n_in,
                              void* d_out, int out_size)
{
    const float* nodes   = (const float*)d_in[0];
    const float* pos     = (const float*)d_in[1];
    const float* attmap  = (const float*)d_in[2];
    const float* conv1_w = (const float*)d_in[4];
    const float* conv1_b = (const float*)d_in[5];
    const float* conv2_w = (const float*)d_in[6];
    const float* conv2_b = (const float*)d_in[7];
    const float* lin_w   = (const float*)d_in[8];
    const float* lin_b   = (const float*)d_in[9];
    const float* wfc_w   = (const float*)d_in[10];
    const float* wfc_b   = (const float*)d_in[11];
    const float* fm_w    = (const float*)d_in[12];
    const float* fm_b    = (const float*)d_in[13];
    const float* lm_w    = (const float*)d_in[14];
    const float* lm_b    = (const float*)d_in[15];
    const float* fc1_w   = (const float*)d_in[16];
    const float* fc1_b   = (const float*)d_in[17];
    const float* fc2_w   = (const float*)d_in[18];
    const float* fc2_b   = (const float*)d_in[19];
    const float* fc3_w   = (const float*)d_in[20];
    const float* fc3_b   = (const float*)d_in[21];
    float* out = (float*)d_out;

    fused_kernel<<<NBLK, 256>>>(nodes, pos, attmap,
                                conv1_w, conv1_b, conv2_w, conv2_b,
                                lin_w, lin_b, wfc_w, wfc_b, fm_w, fm_b,
                                lm_w, lm_b, fc1_w, fc1_b, fc2_w, fc2_b,
                                fc3_w, fc3_b, out);
}

// round 7
// speedup vs baseline: 1.0796x; 1.0796x over previous
#include <cuda_runtime.h>
#include <math.h>

// ---------------------------------------------------------------------------
// Shapes: N=16, F=5, V=4 -> 320 images of 3x224x224
// conv1: 3->3, 3x3, s2: 224->111 ; maxpool3/3 -> 37 ; relu
// conv2: 3->1, 3x3, s2: 37->18   ; maxpool3/3 -> 6  ; relu
// flatten 36 -> linear -> feat[320,6]; graph ops + MLP -> [16,6]
//
// Two kernels:
//  K1: conv1+pool+relu, 1712 blocks x 256 thr, one output per thread
//      (proven 37.6us @ 66% DRAM shape, R4). No atomics/fences.
//  K2: epilogue, 320 blocks x 256 thr (all resident: 320 < 444 slots).
//      Each block: conv2+pool+relu+linear for one image -> g_feat.
//      Single-counter ticket; last 16 blocks spin (safe: everyone resident)
//      then run graph ops + readout MLP. Counters reset for graph replay.
// ---------------------------------------------------------------------------

#define NIMG 320
#define H1_STRIDE (3 * 1369)
#define TOTAL1 (NIMG * 1369)
#define NBLK1 1712

__device__ float g_h1[NIMG * H1_STRIDE];
__device__ float g_feat[NIMG * 6];
__device__ int g_cnt = 0, g_done = 0;

// ---------------- Kernel 1: conv1 + maxpool3 + relu (R4 verbatim) ----------
__global__ __launch_bounds__(256, 3)
void conv1_pool_kernel(const float* __restrict__ nodes,
                       const float* __restrict__ w,   // [3,3,3,3] OIHW
                       const float* __restrict__ b)   // [3]
{
    __shared__ float sw[81];
    __shared__ float sb[3];
    int tid = threadIdx.x;
    if (tid < 81) sw[tid] = w[tid];
    if (tid < 3)  sb[tid] = b[tid];
    __syncthreads();

    int idx = blockIdx.x * 256 + tid;
    if (idx >= TOTAL1) return;
    int px  = idx % 37;
    int rem = idx / 37;
    int py  = rem % 37;
    int img = rem / 37;

    const float* base = nodes + (size_t)img * 150528
                              + (size_t)(6 * py) * 224 + 6 * px;

    float acc[9][3];
#pragma unroll
    for (int p = 0; p < 9; p++) {
        acc[p][0] = sb[0]; acc[p][1] = sb[1]; acc[p][2] = sb[2];
    }

#pragma unroll
    for (int ic = 0; ic < 3; ic++) {
        const float* chan = base + ic * 50176;
        float2 p2[7][4];
#pragma unroll
        for (int r = 0; r < 7; r++) {
            const float* rp = chan + r * 224;
            p2[r][0] = *(const float2*)(rp);
            p2[r][1] = *(const float2*)(rp + 2);
            p2[r][2] = *(const float2*)(rp + 4);
            p2[r][3] = *(const float2*)(rp + 6);
        }
#pragma unroll
        for (int ky = 0; ky < 3; ky++)
#pragma unroll
            for (int kx = 0; kx < 3; kx++) {
                float w0 = sw[ic * 9 + ky * 3 + kx];
                float w1 = sw[27 + ic * 9 + ky * 3 + kx];
                float w2 = sw[54 + ic * 9 + ky * 3 + kx];
#pragma unroll
                for (int cy = 0; cy < 3; cy++)
#pragma unroll
                    for (int cx = 0; cx < 3; cx++) {
                        int col = 2 * cx + kx;
                        float v = (col & 1) ? p2[2 * cy + ky][col >> 1].y
                                            : p2[2 * cy + ky][col >> 1].x;
                        acc[cy * 3 + cx][0] += v * w0;
                        acc[cy * 3 + cx][1] += v * w1;
                        acc[cy * 3 + cx][2] += v * w2;
                    }
            }
    }

#pragma unroll
    for (int oc = 0; oc < 3; oc++) {
        float m = acc[0][oc];
#pragma unroll
        for (int p = 1; p < 9; p++) m = fmaxf(m, acc[p][oc]);
        m = fmaxf(m, 0.0f);
        g_h1[(size_t)img * H1_STRIDE + oc * 1369 + py * 37 + px] = m;
    }
}

// ---------------- Kernel 2: epilogue (conv2+feat, then graph+readout) ------
__global__ __launch_bounds__(256)
void epilogue_kernel(const float* __restrict__ pos,     // [16,5,4,6]
                     const float* __restrict__ attmap,  // [16,5,4,4]
                     const float* __restrict__ c2w, const float* __restrict__ c2b,
                     const float* __restrict__ lw,  const float* __restrict__ lb,
                     const float* __restrict__ wfc_w, const float* __restrict__ wfc_b,
                     const float* __restrict__ fm_w,  const float* __restrict__ fm_b,
                     const float* __restrict__ lm_w,  const float* __restrict__ lm_b,
                     const float* __restrict__ fc1_w, const float* __restrict__ fc1_b,
                     const float* __restrict__ fc2_w, const float* __restrict__ fc2_b,
                     const float* __restrict__ fc3_w, const float* __restrict__ fc3_b,
                     float* __restrict__ out)           // [16,6]
{
    __shared__ float sw2[27];
    __shared__ float s_conv[36][9];
    __shared__ float s_hs[36];
    __shared__ int   s_tick;
    __shared__ float r_feat[20][6];
    __shared__ float r_ps[20][6];
    __shared__ float r_asrc[20];
    __shared__ float r_btgt[20];
    __shared__ float r_pm[20][6];
    __shared__ float r_inp[240];
    __shared__ float r_part[240];
    __shared__ float r_r1[120];
    __shared__ float r_r2[60];

    const int img = blockIdx.x;
    const int t   = threadIdx.x;
    if (t < 27) sw2[t] = c2w[t];
    __syncthreads();

    // conv2(s2) + maxpool3 + relu + linear (g_h1 is L2-resident)
    for (int posn = t; posn < 324; posn += 256) {
        int pool = posn / 9, cp = posn - pool * 9;
        int py = pool / 6, px = pool - py * 6;
        int cy = 3 * py + cp / 3;
        int cx = 3 * px + cp % 3;
        const float* src = g_h1 + (size_t)img * H1_STRIDE + (2 * cy) * 37 + 2 * cx;
        float s = __ldg(c2b);
#pragma unroll
        for (int ic = 0; ic < 3; ic++)
#pragma unroll
            for (int ky = 0; ky < 3; ky++)
#pragma unroll
                for (int kx = 0; kx < 3; kx++)
                    s += src[ic * 1369 + ky * 37 + kx] * sw2[ic * 9 + ky * 3 + kx];
        s_conv[pool][cp] = s;
    }
    __syncthreads();
    if (t < 36) {
        float m = s_conv[t][0];
#pragma unroll
        for (int p = 1; p < 9; p++) m = fmaxf(m, s_conv[t][p]);
        s_hs[t] = fmaxf(m, 0.0f);
    }
    __syncthreads();
    if (t < 6) {
        float s = __ldg(lb + t);
#pragma unroll
        for (int i = 0; i < 36; i++) s += s_hs[i] * __ldg(lw + i * 6 + t);
        g_feat[img * 6 + t] = s;
    }
    __syncthreads();

    // release + ticket (t0 only; syncthreads gives block-scope cumulativity)
    if (t == 0) {
        __threadfence();
        s_tick = atomicAdd(&g_cnt, 1);
    }
    __syncthreads();
    int tick = s_tick;
    if (tick < NIMG - 16) return;       // not one of the last 16 finishers

    const int n = tick - (NIMG - 16);
    if (t == 0) {
        while (atomicAdd(&g_cnt, 0) < NIMG) __nanosleep(64);
        __threadfence();                 // acquire
    }
    __syncthreads();

    // ---------------- graph ops + readout MLP ----------------
    if (t < 120) {
        int fv = t / 6, d = t % 6;
        r_feat[fv][d] = g_feat[(n * 20 + fv) * 6 + d];
        r_ps[fv][d]   = pos[(n * 20 + fv) * 6 + d];
    }
    __syncthreads();

    if (t < 20) {
        float a = 0.0f, bb = 0.0f;
#pragma unroll
        for (int k = 0; k < 6; k++) {
            a  += r_feat[t][k] * wfc_w[k]      + r_ps[t][k] * wfc_w[6 + k];
            bb += r_feat[t][k] * wfc_w[12 + k] + r_ps[t][k] * wfc_w[18 + k];
        }
        r_asrc[t] = a;
        r_btgt[t] = bb;
    }
    if (t < 120) {
        int fv = t / 6, d = t % 6;
        float s = fm_b[d];
#pragma unroll
        for (int k = 0; k < 6; k++) s += r_ps[fv][k] * fm_w[k * 6 + d];
        r_pm[fv][d] = s;
    }
    __syncthreads();

    if (t < 120) {
        int fv = t / 6, d = t % 6;
        int f = fv / 4, tv = fv % 4;
        float bias = wfc_b[0];
        float agg = 0.0f;
#pragma unroll
        for (int s = 0; s < 4; s++) {
            float z  = r_asrc[f * 4 + s] + r_btgt[f * 4 + tv] + bias;
            float lk = 1.0f / (1.0f + expf(-z));
            float m  = lk + attmap[((n * 5 + f) * 4 + s) * 4 + tv];
            agg += m * r_pm[f * 4 + s][d];
        }
        if (f > 0) {
            float lm = lm_b[d];
#pragma unroll
            for (int k = 0; k < 6; k++) lm += r_ps[(f - 1) * 4 + tv][k] * lm_w[k * 6 + d];
            agg += lm;
        }
        r_inp[fv * 12 + d]     = r_feat[fv][d];
        r_inp[fv * 12 + 6 + d] = agg;
    }
    __syncthreads();

    if (t < 240) {                       // fc1: 240x120, split over 2 halves
        int half = t / 120, j = t - half * 120;
        int i0 = half * 120;
        float s = 0.0f;
#pragma unroll 12
        for (int i = 0; i < 120; i++)
            s += r_inp[i0 + i] * __ldg(fc1_w + (i0 + i) * 120 + j);
        r_part[t] = s;
    }
    __syncthreads();
    if (t < 120) r_r1[t] = fmaxf(r_part[t] + r_part[120 + t] + __ldg(fc1_b + t), 0.0f);
    __syncthreads();

    if (t < 120) {                       // fc2: 120x60, split over 2 halves
        int half = t / 60, j = t - half * 60;
        int i0 = half * 60;
        float s = 0.0f;
#pragma unroll 12
        for (int i = 0; i < 60; i++)
            s += r_r1[i0 + i] * __ldg(fc2_w + (i0 + i) * 60 + j);
        r_part[t] = s;
    }
    __syncthreads();
    if (t < 60) r_r2[t] = fmaxf(r_part[t] + r_part[60 + t] + __ldg(fc2_b + t), 0.0f);
    __syncthreads();

    if (t < 6) {
        float s = __ldg(fc3_b + t);
#pragma unroll
        for (int i = 0; i < 60; i++) s += r_r2[i] * __ldg(fc3_w + i * 6 + t);
        out[n * 6 + t] = s;
    }
    __syncthreads();

    // deterministic counter reset for graph replay
    if (t == 0) {
        int r = atomicAdd(&g_done, 1);
        if (r == 15) {
            g_cnt = 0;
            __threadfence();
            g_done = 0;
        }
    }
}

// ---------------------------------------------------------------------------
extern "C" void kernel_launch(void* const* d_in, const int* in_sizes, int n_in,
                              void* d_out, int out_size)
{
    const float* nodes   = (const float*)d_in[0];
    const float* pos     = (const float*)d_in[1];
    const float* attmap  = (const float*)d_in[2];
    const float* conv1_w = (const float*)d_in[4];
    const float* conv1_b = (const float*)d_in[5];
    const float* conv2_w = (const float*)d_in[6];
    const float* conv2_b = (const float*)d_in[7];
    const float* lin_w   = (const float*)d_in[8];
    const float* lin_b   = (const float*)d_in[9];
    const float* wfc_w   = (const float*)d_in[10];
    const float* wfc_b   = (const float*)d_in[11];
    const float* fm_w    = (const float*)d_in[12];
    const float* fm_b    = (const float*)d_in[13];
    const float* lm_w    = (const float*)d_in[14];
    const float* lm_b    = (const float*)d_in[15];
    const float* fc1_w   = (const float*)d_in[16];
    const float* fc1_b   = (const float*)d_in[17];
    const float* fc2_w   = (const float*)d_in[18];
    const float* fc2_b   = (const float*)d_in[19];
    const float* fc3_w   = (const float*)d_in[20];
    const float* fc3_b   = (const float*)d_in[21];
    float* out = (float*)d_out;

    conv1_pool_kernel<<<NBLK1, 256>>>(nodes, conv1_w, conv1_b);
    epilogue_kernel<<<NIMG, 256>>>(pos, attmap, conv2_w, conv2_b,
                                   lin_w, lin_b, wfc_w, wfc_b, fm_w, fm_b,
                                   lm_w, lm_b, fc1_w, fc1_b, fc2_w, fc2_b,
                                   fc3_w, fc3_b, out);
}